// round 12
// baseline (speedup 1.0000x reference)
#include <cuda_runtime.h>

// STTEncoder: replicate the reference's fp32 integral image bitwise.
// jnp.cumsum -> reduce_window -> XLA ReduceWindowRewriter(base=16):
// blocked-sequential recursive scan (PASS since R7, rel_err 1.6e-8).
// R12: fuse stage1 (x-scan) + stage2a (y level-1 fold): one block owns
// y-block r x one bc, streams its 16 disjoint image rows via cp.async,
// x-scans each row into smem, y-folds from smem. Kills the 173MB g_Sx
// round-trip. All rounding orders preserved op-for-op.

#define IMG_W 1280
#define TS 16
constexpr int NTOK = 172;
constexpr int N1 = IMG_W + 1;   // padded scan length (1281)
constexpr int NB1 = 81;         // ceil(1281/16)
constexpr int NB1P = 96;        // padded to 6*16
constexpr int NB2 = 6;

struct Tok { int x, y, s; };
struct Table { Tok t[NTOK]; int count; };

constexpr Table make_table() {
    Table tb{};
    constexpr int STR[5] = {1, 2, 4, 6, 8};
    constexpr int GRD[5] = {4, 4, 6, 8, 10};
    int n = 0;
    int plo = 0, phi = 0;
    bool has = false;
    for (int sc = 0; sc < 5; ++sc) {
        int s = STR[sc], g = GRD[sc];
        int cov = g * TS * s;
        int off = (IMG_W - cov) / 2;
        for (int j = 0; j < g; ++j)
            for (int i = 0; i < g; ++i) {
                int x = off + i * TS * s;
                int y = off + j * TS * s;
                if (has && x >= plo && x + TS * s <= phi &&
                    y >= plo && y + TS * s <= phi)
                    continue;
                tb.t[n].x = x; tb.t[n].y = y; tb.t[n].s = s; ++n;
            }
        plo = off; phi = off + cov; has = true;
    }
    tb.count = n;
    return tb;
}
static_assert(make_table().count == NTOK, "token count mismatch");
__constant__ Table TOKS = make_table();

// ---- needed boundary coordinate set (same for x and y) ----
struct BMask { bool m[N1]; };
constexpr BMask make_bmask() {
    BMask b{};
    Table tb = make_table();
    for (int t = 0; t < NTOK; ++t) {
        int s = tb.t[t].s;
        for (int i = 0; i <= TS; ++i) {
            b.m[tb.t[t].x + s * i] = true;
            b.m[tb.t[t].y + s * i] = true;
        }
    }
    return b;
}
constexpr int count_bounds() {
    BMask b = make_bmask(); int c = 0;
    for (int i = 0; i < N1; ++i) if (b.m[i]) ++c;
    return c;
}
constexpr int NX = count_bounds();
static_assert(NX <= 512, "boundary set too large");
constexpr int NX32 = (NX + 31) / 32 * 32;
constexpr int NCG = NX32 / 32;              // column groups

struct BMapT { short cmap[N1]; };
constexpr BMapT make_bmap() {
    BMapT r{};
    BMask b = make_bmask();
    int c = 0;
    for (int i = 0; i < N1; ++i) {
        if (b.m[i]) { r.cmap[i] = (short)c; ++c; }
        else r.cmap[i] = -1;
    }
    return r;
}
__device__ const BMapT BMAP = make_bmap();

// per-16-block needed-position mask + cumulative output base
struct BlkInfo { unsigned short mask; short base; };
struct BlkTab { BlkInfo b[NB1]; int total; };
constexpr BlkTab make_blk() {
    BlkTab t{};
    BMask m = make_bmask();
    int cnt = 0;
    for (int r = 0; r < NB1; ++r) {
        t.b[r].base = (short)cnt;
        unsigned short msk = 0;
        for (int j = 0; j < 16; ++j) {
            int i = r * 16 + j;
            if (i < N1 && m.m[i]) { msk |= (unsigned short)(1u << j); ++cnt; }
        }
        t.b[r].mask = msk;
    }
    t.total = cnt;
    return t;
}
static_assert(make_blk().total == NX, "mask/base table inconsistent");
__device__ const BlkTab BLK = make_blk();

// block index (coord>>4) of each sampled coordinate (stage 3)
struct RTab { short r[NX]; };
constexpr RTab make_rtab() {
    RTab t{};
    BMask b = make_bmask();
    int c = 0;
    for (int i = 0; i < N1; ++i)
        if (b.m[i]) { t.r[c] = (short)(i >> 4); ++c; }
    return t;
}
__device__ const RTab RBLK = make_rtab();

// x-sample table: pfx word index | (block r << 16), in cmap order
constexpr int PFXW = 1456;
struct STab { int v[NX]; };
constexpr STab make_stab() {
    STab t{};
    BMask b = make_bmask();
    int c = 0;
    for (int i = 0; i < N1; ++i)
        if (b.m[i]) {
            const int r = i >> 4, j = i & 15;
            const int w = 16 * r + 4 * (r >> 1) + j;
            t.v[c] = w | (r << 16);
            ++c;
        }
    return t;
}
__device__ const STab SPOS = make_stab();

// ---- scratch (device globals: no allocation allowed) ----
__device__ float g_P[48ull * NX * NX32];         // sampled level-1 y-prefixes
__device__ float g_B[48ull * NB1 * NX32];        // y block sums
__device__ float g_Add[48ull * NB1 * NX32];      // add[r][col] = off2+b2prefix

// ============ Fused stage 1+2a: x-scans + y level-1 fold per y-block ========
// raw/pfx layout: float4 j at word 4j+4*(j>>3); x-block rr's 16 words
// contiguous at W(rr)=16rr+4*(rr>>1). STS.128/LDS.128 conflict-free.
__global__ __launch_bounds__(256) void stt_stage12(const float* __restrict__ img) {
    __shared__ __align__(16) float raw[2][1440];
    __shared__ __align__(16) float pfx[PFXW];
    __shared__ __align__(16) float s_bsum[NB1P];
    __shared__ float s_off2[NB2];
    __shared__ float s_add[NB1];
    __shared__ float xs[16][NX32];   // sampled x-prefixes of the 16 padded rows

    const int r  = blockIdx.x;       // y-block index
    const int bc = blockIdx.y;
    const int t  = threadIdx.x;      // 0..255

    const float* ibase = img + (size_t)bc * (IMG_W * IMG_W);

    // issue cp.async loads of image row yy(j) into raw[buf]; always commits
    auto issue_row = [&](int j, int buf) {
        const int yy = r * 16 + j - 1;
        if (yy >= 0 && yy < IMG_W) {
            const float4* src4 = reinterpret_cast<const float4*>(
                ibase + (size_t)yy * IMG_W);
#pragma unroll
            for (int k = 0; k < 2; ++k) {
                const int j4 = t + k * 256;
                if (j4 < 320) {
                    unsigned sa = (unsigned)__cvta_generic_to_shared(
                        &raw[buf][4 * j4 + 4 * (j4 >> 3)]);
                    asm volatile("cp.async.ca.shared.global [%0], [%1], 16;\n"
                                 :: "r"(sa), "l"(src4 + j4));
                }
            }
        }
        asm volatile("cp.async.commit_group;\n" ::: "memory");
    };

    issue_row(0, 0);
    issue_row(1, 1);

    for (int j = 0; j < 16; ++j) {
        asm volatile("cp.async.wait_group 1;\n" ::: "memory");
        __syncthreads();                       // raw[j&1] ready; prev iter done
        const int yy = r * 16 + j - 1;
        const int buf = j & 1;

        if (yy >= 0 && yy < IMG_W) {
            // ---- x level 1: sequential fold of x-block rr ----
            if (t < NB1) {
                const int rr = t;
                float e0 = 0.f;
                if (rr > 0) {                  // pixel 16rr-1 = float4 4rr-1 elem 3
                    const int jj = 4 * rr - 1;
                    e0 = raw[buf][4 * jj + 4 * (jj >> 3) + 3];
                }
                float acc = 0.f + e0;          // exact: fold init 0 + first elem
                float4 P0 = make_float4(acc, 0.f, 0.f, 0.f);
                float4 P1 = P0, P2 = P0, P3 = P0;
                const int W = 16 * rr + 4 * (rr >> 1);
                if (rr < 80) {
                    const float4 a = *reinterpret_cast<const float4*>(&raw[buf][W]);
                    const float4 b = *reinterpret_cast<const float4*>(&raw[buf][W + 4]);
                    const float4 c = *reinterpret_cast<const float4*>(&raw[buf][W + 8]);
                    const float4 d = *reinterpret_cast<const float4*>(&raw[buf][W + 12]);
                    acc = acc + a.x; P0.y = acc;
                    acc = acc + a.y; P0.z = acc;
                    acc = acc + a.z; P0.w = acc;
                    acc = acc + a.w; P1.x = acc;
                    acc = acc + b.x; P1.y = acc;
                    acc = acc + b.y; P1.z = acc;
                    acc = acc + b.z; P1.w = acc;
                    acc = acc + b.w; P2.x = acc;
                    acc = acc + c.x; P2.y = acc;
                    acc = acc + c.y; P2.z = acc;
                    acc = acc + c.z; P2.w = acc;
                    acc = acc + c.w; P3.x = acc;
                    acc = acc + d.x; P3.y = acc;
                    acc = acc + d.y; P3.z = acc;
                    acc = acc + d.z; P3.w = acc;
                }
                *reinterpret_cast<float4*>(&pfx[W])      = P0;
                *reinterpret_cast<float4*>(&pfx[W + 4])  = P1;
                *reinterpret_cast<float4*>(&pfx[W + 8])  = P2;
                *reinterpret_cast<float4*>(&pfx[W + 12]) = P3;
                s_bsum[rr] = acc;
            } else if (t < NB1P) {
                s_bsum[t] = 0.f;
            }
            __syncthreads();

            // ---- x level 2: register fold of 16 block sums per group ----
            if (t < NB2) {
                float* bs = &s_bsum[t * 16];
                float4 a = *reinterpret_cast<const float4*>(bs);
                float4 b = *reinterpret_cast<const float4*>(bs + 4);
                float4 c = *reinterpret_cast<const float4*>(bs + 8);
                float4 d = *reinterpret_cast<const float4*>(bs + 12);
                float acc = 0.f;
                acc = acc + a.x; a.x = acc;
                acc = acc + a.y; a.y = acc;
                acc = acc + a.z; a.z = acc;
                acc = acc + a.w; a.w = acc;
                acc = acc + b.x; b.x = acc;
                acc = acc + b.y; b.y = acc;
                acc = acc + b.z; b.z = acc;
                acc = acc + b.w; b.w = acc;
                acc = acc + c.x; c.x = acc;
                acc = acc + c.y; c.y = acc;
                acc = acc + c.z; c.z = acc;
                acc = acc + c.w; c.w = acc;
                acc = acc + d.x; d.x = acc;
                acc = acc + d.y; d.y = acc;
                acc = acc + d.z; d.z = acc;
                acc = acc + d.w; d.w = acc;
                *reinterpret_cast<float4*>(bs)      = a;
                *reinterpret_cast<float4*>(bs + 4)  = b;
                *reinterpret_cast<float4*>(bs + 8)  = c;
                *reinterpret_cast<float4*>(bs + 12) = d;
            }
            __syncthreads();

            // ---- x level 3: exclusive fold of group totals ----
            if (t == 0) {
                float acc = 0.f;
                s_off2[0] = 0.f;
#pragma unroll
                for (int u = 0; u < NB2 - 1; ++u) {
                    acc = acc + s_bsum[u * 16 + 15];
                    s_off2[u + 1] = acc;
                }
            }
            __syncthreads();

            // add[rr] = off2[(rr-1)>>4] + b2prefix[rr-1]
            if (t < NB1)
                s_add[t] = (t == 0) ? 0.f : (s_off2[(t - 1) >> 4] + s_bsum[t - 1]);
            __syncthreads();

            // table-driven x-sample gather into xs[j]
            for (int i = t; i < NX; i += 256) {
                const int pk = SPOS.v[i];
                const int w = pk & 0xFFFF, rr = pk >> 16;
                const float p = pfx[w];
                xs[j][i] = rr ? (s_add[rr] + p) : p;
            }
        } else {
            // padded rows (yy=-1 or beyond image): zero contribution
            for (int i = t; i < NX; i += 256) xs[j][i] = 0.f;
        }

        if (j + 2 < 16) issue_row(j + 2, buf);
        else asm volatile("cp.async.commit_group;\n" ::: "memory");
    }
    __syncthreads();                           // all xs rows complete

    // ---- y level-1 fold over the 16 padded rows (exact 2a fold order) ----
    const BlkInfo bi = BLK.b[r];
    for (int c = t; c < NX; c += 256) {
        float acc = 0.f;
        int o = bi.base;
        float* P = g_P + (size_t)bc * NX * NX32 + c;
#pragma unroll
        for (int j = 0; j < 16; ++j) {
            acc = acc + xs[j][c];
            if ((bi.mask >> j) & 1) { P[(size_t)o * NX32] = acc; ++o; }
        }
        g_B[((size_t)bc * NB1 + r) * NX32 + c] = acc;
    }
}

// ===== Stage 2b: exact level-2/3 combine over block sums (per column) =======
__global__ __launch_bounds__(32) void stt_stage2b() {
    const int col = blockIdx.x * 32 + threadIdx.x;
    const int bc  = blockIdx.y;
    const float* B = g_B   + (size_t)bc * NB1 * NX32 + col;
    float*       A = g_Add + (size_t)bc * NB1 * NX32 + col;

    float acc2 = 0.f;     // b2prefix[r-1] at block entry
    float off_cur = 0.f;  // off2[current group]
#pragma unroll 4
    for (int r = 0; r < NB1; ++r) {
        const float Bv = B[(size_t)r * NX32];
        const float off_used = off_cur;
        if (r > 0 && (r & 15) == 0)
            off_cur = off_cur + acc2;            // off2[u] = off2[u-1]+total[u-1]
        A[(size_t)r * NX32] = off_used + acc2;   // add[r] (r=0 slot unused)
        acc2 = ((r & 15) == 0) ? Bv : (acc2 + Bv);
    }
}

// ====== Stage 3: fused final offset-add + 4-corner gather + divide ==========
__global__ __launch_bounds__(256) void stt_stage3(float* __restrict__ out) {
    const int tok = blockIdx.x;
    const int bc  = blockIdx.y;
    const Tok t = TOKS.t[tok];
    const int tx = threadIdx.x, ty = threadIdx.y;

    const int xl = t.x + t.s * tx, xu = xl + t.s;
    const int yl = t.y + t.s * ty, yu = yl + t.s;
    const int cxl = BMAP.cmap[xl], cxu = BMAP.cmap[xu];
    const int cyl = BMAP.cmap[yl], cyu = BMAP.cmap[yu];

    const float* P   = g_P   + (size_t)bc * NX * NX32;
    const float* Add = g_Add + (size_t)bc * NB1 * NX32;

    // ii(yc,xc) = r==0 ? p : add[r] + p   (single rounded add, exact order)
    auto iival = [&](int yc, int xc) -> float {
        float v = P[(size_t)yc * NX32 + xc];
        const int r = RBLK.r[yc];
        if (r > 0) v = Add[(size_t)r * NX32 + xc] + v;
        return v;
    };

    const float A = iival(cyu, cxu);
    const float B = iival(cyu, cxl);
    const float C = iival(cyl, cxu);
    const float D = iival(cyl, cxl);
    const float box = ((A - B) - C) + D;   // reference op order

    const int b = bc / 3, ch = bc % 3;
    const size_t o = ((((size_t)b * NTOK + tok) * 3 + ch) * TS + ty) * TS + tx;
    out[o] = box / (float)(t.s * t.s);
}

extern "C" void kernel_launch(void* const* d_in, const int* in_sizes, int n_in,
                              void* d_out, int out_size) {
    const float* img = (const float*)d_in[0];
    float* out = (float*)d_out;

    dim3 g12(NB1, 48);
    stt_stage12<<<g12, 256>>>(img);

    dim3 g2b(NCG, 48);
    stt_stage2b<<<g2b, 32>>>();

    dim3 g3(NTOK, 48);
    stt_stage3<<<g3, dim3(TS, TS)>>>(out);
}

// round 13
// speedup vs baseline: 1.0442x; 1.0442x over previous
#include <cuda_runtime.h>

// STTEncoder: replicate the reference's fp32 integral image bitwise.
// jnp.cumsum -> reduce_window -> XLA ReduceWindowRewriter(base=16):
// blocked-sequential recursive scan (PASS since R7, rel_err 1.6e-8).
// R13: fused stage1+2a, warp-parallel: 16 warps/block, one warp per image
// row, warp-synchronous x-scan (cp.async double-buffered chunks, lane-owns-
// block folds, shfl boundaries), then one block sync + y-fold. 2b/s3 as R12.

#define IMG_W 1280
#define TS 16
constexpr int NTOK = 172;
constexpr int N1 = IMG_W + 1;   // padded scan length (1281)
constexpr int NB1 = 81;         // ceil(1281/16)
constexpr int NB2 = 6;

struct Tok { int x, y, s; };
struct Table { Tok t[NTOK]; int count; };

constexpr Table make_table() {
    Table tb{};
    constexpr int STR[5] = {1, 2, 4, 6, 8};
    constexpr int GRD[5] = {4, 4, 6, 8, 10};
    int n = 0;
    int plo = 0, phi = 0;
    bool has = false;
    for (int sc = 0; sc < 5; ++sc) {
        int s = STR[sc], g = GRD[sc];
        int cov = g * TS * s;
        int off = (IMG_W - cov) / 2;
        for (int j = 0; j < g; ++j)
            for (int i = 0; i < g; ++i) {
                int x = off + i * TS * s;
                int y = off + j * TS * s;
                if (has && x >= plo && x + TS * s <= phi &&
                    y >= plo && y + TS * s <= phi)
                    continue;
                tb.t[n].x = x; tb.t[n].y = y; tb.t[n].s = s; ++n;
            }
        plo = off; phi = off + cov; has = true;
    }
    tb.count = n;
    return tb;
}
static_assert(make_table().count == NTOK, "token count mismatch");
__constant__ Table TOKS = make_table();

// ---- needed boundary coordinate set (same for x and y) ----
struct BMask { bool m[N1]; };
constexpr BMask make_bmask() {
    BMask b{};
    Table tb = make_table();
    for (int t = 0; t < NTOK; ++t) {
        int s = tb.t[t].s;
        for (int i = 0; i <= TS; ++i) {
            b.m[tb.t[t].x + s * i] = true;
            b.m[tb.t[t].y + s * i] = true;
        }
    }
    return b;
}
constexpr int count_bounds() {
    BMask b = make_bmask(); int c = 0;
    for (int i = 0; i < N1; ++i) if (b.m[i]) ++c;
    return c;
}
constexpr int NX = count_bounds();
static_assert(NX <= 512, "boundary set too large");
constexpr int NX32 = (NX + 31) / 32 * 32;
constexpr int NCG = NX32 / 32;

struct BMapT { short cmap[N1]; };
constexpr BMapT make_bmap() {
    BMapT r{};
    BMask b = make_bmask();
    int c = 0;
    for (int i = 0; i < N1; ++i) {
        if (b.m[i]) { r.cmap[i] = (short)c; ++c; }
        else r.cmap[i] = -1;
    }
    return r;
}
__device__ const BMapT BMAP = make_bmap();

// per-16-block needed-position mask + cumulative output base
struct BlkInfo { unsigned short mask; short base; };
struct BlkTab { BlkInfo b[NB1]; int total; };
constexpr BlkTab make_blk() {
    BlkTab t{};
    BMask m = make_bmask();
    int cnt = 0;
    for (int r = 0; r < NB1; ++r) {
        t.b[r].base = (short)cnt;
        unsigned short msk = 0;
        for (int j = 0; j < 16; ++j) {
            int i = r * 16 + j;
            if (i < N1 && m.m[i]) { msk |= (unsigned short)(1u << j); ++cnt; }
        }
        t.b[r].mask = msk;
    }
    t.total = cnt;
    return t;
}
static_assert(make_blk().total == NX, "mask/base table inconsistent");
__device__ const BlkTab BLK = make_blk();

// x/y-block index of each sampled coordinate
struct RTab { short r[NX]; };
constexpr RTab make_rtab() {
    RTab t{};
    BMask b = make_bmask();
    int c = 0;
    for (int i = 0; i < N1; ++i)
        if (b.m[i]) { t.r[c] = (short)(i >> 4); ++c; }
    return t;
}
__device__ const RTab RBLK = make_rtab();

// ---- scratch (device globals: no allocation allowed) ----
__device__ float g_P[48ull * NX * NX32];     // sampled level-1 y-prefixes
__device__ float g_B[48ull * NB1 * NX32];    // y block sums
__device__ float g_Add[48ull * NB1 * NX32];  // add[r][col]

// dynamic smem layout (words)
constexpr int CHW    = 576;                // padded words per chunk buffer
constexpr int SM_BUF = 16 * 2 * CHW;       // per-warp double-buffered chunks
constexpr int SM_XS  = 16 * NX32;          // sampled x-prefixes per row
constexpr int SM_BS  = 16 * 96;            // per-warp block sums (padded)
constexpr int SM_ADD = 16 * 84;            // per-warp add table
constexpr int SMEM_WORDS = SM_BUF + SM_XS + SM_BS + SM_ADD;

// ============ Fused stage 1+2a: one warp per row, warp-synchronous ==========
__global__ __launch_bounds__(512) void stt_stage12(const float* __restrict__ img) {
    extern __shared__ __align__(16) float smem[];
    float* bufs = smem;
    float* xs   = smem + SM_BUF;
    float* bsA  = xs + SM_XS;
    float* adA  = bsA + SM_BS;

    const int r  = blockIdx.x;       // y-block
    const int bc = blockIdx.y;
    const int t  = threadIdx.x;
    const int w  = t >> 5, l = t & 31;

    float* buf_w  = bufs + w * (2 * CHW);
    float* xs_w   = xs + w * NX32;
    float* bsum_w = bsA + w * 96;
    float* sadd_w = adA + w * 84;

    const int yy = r * 16 + w - 1;   // padded row element index -> image row
    const bool valid = (yy >= 0) && (yy < IMG_W);

    if (valid) {
        const float* row = img + ((size_t)bc * IMG_W + yy) * IMG_W;

        auto issue_chunk = [&](int c) {
            const int nf4 = (c < 2) ? 128 : 64;      // chunk2 = 256 px
            const float4* s4 = reinterpret_cast<const float4*>(row) + 128 * c;
            float* db = buf_w + (c & 1) * CHW;
#pragma unroll
            for (int k = 0; k < 4; ++k) {
                const int j = 32 * k + l;
                if (j < nf4) {
                    unsigned sa = (unsigned)__cvta_generic_to_shared(
                        &db[4 * j + 4 * (j >> 3)]);
                    asm volatile("cp.async.ca.shared.global [%0], [%1], 16;\n"
                                 :: "r"(sa), "l"(s4 + j));
                }
            }
            asm volatile("cp.async.commit_group;\n" ::: "memory");
        };

        issue_chunk(0);
        issue_chunk(1);

        float carry = 0.f;
        for (int c = 0; c < 3; ++c) {
            asm volatile("cp.async.wait_group 1;\n" ::: "memory");
            __syncwarp();
            const float* db = buf_w + (c & 1) * CHW;
            float4 a = make_float4(0.f, 0.f, 0.f, 0.f);
            float4 b = a, cv = a, d = a;
            const bool loads = (c < 2) || (l < 16);
            if (loads) {
                const int W = 16 * l + 4 * (l >> 1);
                a  = *reinterpret_cast<const float4*>(&db[W]);
                b  = *reinterpret_cast<const float4*>(&db[W + 4]);
                cv = *reinterpret_cast<const float4*>(&db[W + 8]);
                d  = *reinterpret_cast<const float4*>(&db[W + 12]);
            }
            const float last = d.w;
            float e0 = __shfl_up_sync(0xffffffffu, last, 1);
            if (l == 0) e0 = carry;                 // chunk boundary / global pad
            const int B = 32 * c + l;
            const bool doB = ((c < 2) || (l <= 16)) && (B <= 80);
            if (doB) {
                const BlkInfo bi = BLK.b[B];
                const unsigned m = bi.mask;
                int o = bi.base;
                float acc = 0.f + e0;               // exact: fold init 0 + elem0
                if (m & 1u) xs_w[o++] = acc;
                if (B < 80) {
                    acc = acc + a.x;  if (m & (1u << 1))  xs_w[o++] = acc;
                    acc = acc + a.y;  if (m & (1u << 2))  xs_w[o++] = acc;
                    acc = acc + a.z;  if (m & (1u << 3))  xs_w[o++] = acc;
                    acc = acc + a.w;  if (m & (1u << 4))  xs_w[o++] = acc;
                    acc = acc + b.x;  if (m & (1u << 5))  xs_w[o++] = acc;
                    acc = acc + b.y;  if (m & (1u << 6))  xs_w[o++] = acc;
                    acc = acc + b.z;  if (m & (1u << 7))  xs_w[o++] = acc;
                    acc = acc + b.w;  if (m & (1u << 8))  xs_w[o++] = acc;
                    acc = acc + cv.x; if (m & (1u << 9))  xs_w[o++] = acc;
                    acc = acc + cv.y; if (m & (1u << 10)) xs_w[o++] = acc;
                    acc = acc + cv.z; if (m & (1u << 11)) xs_w[o++] = acc;
                    acc = acc + cv.w; if (m & (1u << 12)) xs_w[o++] = acc;
                    acc = acc + d.x;  if (m & (1u << 13)) xs_w[o++] = acc;
                    acc = acc + d.y;  if (m & (1u << 14)) xs_w[o++] = acc;
                    acc = acc + d.z;  if (m & (1u << 15)) xs_w[o++] = acc;
                }
                bsum_w[B] = acc;
            }
            carry = __shfl_sync(0xffffffffu, last, 31);
            __syncwarp();                           // all LDS done -> buffer free
            if (c == 0) issue_chunk(2);
            else asm volatile("cp.async.commit_group;\n" ::: "memory");
        }

        if (l < 15) bsum_w[81 + l] = 0.f;           // padded block sums
        __syncwarp();

        // level 2: lanes 0..5, register fold of 16 block sums (in place)
        if (l < 6) {
            float* bs = bsum_w + l * 16;
            float4 A = *reinterpret_cast<const float4*>(bs);
            float4 Bv = *reinterpret_cast<const float4*>(bs + 4);
            float4 C = *reinterpret_cast<const float4*>(bs + 8);
            float4 D = *reinterpret_cast<const float4*>(bs + 12);
            float acc = 0.f;
            acc = acc + A.x;  A.x = acc;
            acc = acc + A.y;  A.y = acc;
            acc = acc + A.z;  A.z = acc;
            acc = acc + A.w;  A.w = acc;
            acc = acc + Bv.x; Bv.x = acc;
            acc = acc + Bv.y; Bv.y = acc;
            acc = acc + Bv.z; Bv.z = acc;
            acc = acc + Bv.w; Bv.w = acc;
            acc = acc + C.x;  C.x = acc;
            acc = acc + C.y;  C.y = acc;
            acc = acc + C.z;  C.z = acc;
            acc = acc + C.w;  C.w = acc;
            acc = acc + D.x;  D.x = acc;
            acc = acc + D.y;  D.y = acc;
            acc = acc + D.z;  D.z = acc;
            acc = acc + D.w;  D.w = acc;
            *reinterpret_cast<float4*>(bs)      = A;
            *reinterpret_cast<float4*>(bs + 4)  = Bv;
            *reinterpret_cast<float4*>(bs + 8)  = C;
            *reinterpret_cast<float4*>(bs + 12) = D;
        }
        __syncwarp();

        // level 3: lane 0, exclusive fold of group totals; broadcast
        float o1 = 0.f, o2 = 0.f, o3 = 0.f, o4 = 0.f, o5 = 0.f;
        if (l == 0) {
            float acc = 0.f;
            acc = acc + bsum_w[15]; o1 = acc;
            acc = acc + bsum_w[31]; o2 = acc;
            acc = acc + bsum_w[47]; o3 = acc;
            acc = acc + bsum_w[63]; o4 = acc;
            acc = acc + bsum_w[79]; o5 = acc;
        }
        o1 = __shfl_sync(0xffffffffu, o1, 0);
        o2 = __shfl_sync(0xffffffffu, o2, 0);
        o3 = __shfl_sync(0xffffffffu, o3, 0);
        o4 = __shfl_sync(0xffffffffu, o4, 0);
        o5 = __shfl_sync(0xffffffffu, o5, 0);

        // add[rr] = off2[(rr-1)>>4] + b2prefix[rr-1]
#pragma unroll
        for (int q = 0; q < 3; ++q) {
            const int rr = l + 32 * q;
            if (rr <= 80) {
                float v = 0.f;
                if (rr > 0) {
                    const int g = (rr - 1) >> 4;
                    const float off = (g == 0) ? 0.f : (g == 1) ? o1 :
                                      (g == 2) ? o2 : (g == 3) ? o3 :
                                      (g == 4) ? o4 : o5;
                    v = off + bsum_w[rr - 1];
                }
                sadd_w[rr] = v;
            }
        }
        __syncwarp();

        // transform xs in place: p -> S = (rr ? add[rr] + p : p)
        for (int i = l; i < NX; i += 32) {
            const int rr = RBLK.r[i];
            float v = xs_w[i];
            if (rr > 0) v = sadd_w[rr] + v;
            xs_w[i] = v;
        }
    } else {
        for (int i = l; i < NX; i += 32) xs_w[i] = 0.f;  // padded rows
    }
    __syncthreads();

    // ---- y level-1 fold over the 16 padded rows (exact fold order) ----
    if (t < NX) {
        const BlkInfo bi = BLK.b[r];
        float acc = 0.f;
        int o = bi.base;
        float* P = g_P + (size_t)bc * NX * NX32 + t;
        const float* x0 = xs + t;
#pragma unroll
        for (int j = 0; j < 16; ++j) {
            acc = acc + x0[j * NX32];
            if ((bi.mask >> j) & 1) { P[(size_t)o * NX32] = acc; ++o; }
        }
        g_B[((size_t)bc * NB1 + r) * NX32 + t] = acc;
    }
}

// ===== Stage 2b: exact level-2/3 combine over block sums (per column) =======
__global__ __launch_bounds__(32) void stt_stage2b() {
    const int col = blockIdx.x * 32 + threadIdx.x;
    const int bc  = blockIdx.y;
    const float* B = g_B   + (size_t)bc * NB1 * NX32 + col;
    float*       A = g_Add + (size_t)bc * NB1 * NX32 + col;

    float acc2 = 0.f;     // b2prefix[r-1] at block entry
    float off_cur = 0.f;  // off2[current group]
#pragma unroll 4
    for (int r = 0; r < NB1; ++r) {
        const float Bv = B[(size_t)r * NX32];
        const float off_used = off_cur;
        if (r > 0 && (r & 15) == 0)
            off_cur = off_cur + acc2;            // off2[u] = off2[u-1]+total[u-1]
        A[(size_t)r * NX32] = off_used + acc2;   // add[r] (r=0 slot unused)
        acc2 = ((r & 15) == 0) ? Bv : (acc2 + Bv);
    }
}

// ====== Stage 3: fused final offset-add + 4-corner gather + divide ==========
__global__ __launch_bounds__(256) void stt_stage3(float* __restrict__ out) {
    const int tok = blockIdx.x;
    const int bc  = blockIdx.y;
    const Tok t = TOKS.t[tok];
    const int tx = threadIdx.x, ty = threadIdx.y;

    const int xl = t.x + t.s * tx, xu = xl + t.s;
    const int yl = t.y + t.s * ty, yu = yl + t.s;
    const int cxl = BMAP.cmap[xl], cxu = BMAP.cmap[xu];
    const int cyl = BMAP.cmap[yl], cyu = BMAP.cmap[yu];

    const float* P   = g_P   + (size_t)bc * NX * NX32;
    const float* Add = g_Add + (size_t)bc * NB1 * NX32;

    auto iival = [&](int yc, int xc) -> float {
        float v = P[(size_t)yc * NX32 + xc];
        const int r = RBLK.r[yc];
        if (r > 0) v = Add[(size_t)r * NX32 + xc] + v;
        return v;
    };

    const float A = iival(cyu, cxu);
    const float B = iival(cyu, cxl);
    const float C = iival(cyl, cxu);
    const float D = iival(cyl, cxl);
    const float box = ((A - B) - C) + D;   // reference op order

    const int b = bc / 3, ch = bc % 3;
    const size_t o = ((((size_t)b * NTOK + tok) * 3 + ch) * TS + ty) * TS + tx;
    out[o] = box / (float)(t.s * t.s);
}

extern "C" void kernel_launch(void* const* d_in, const int* in_sizes, int n_in,
                              void* d_out, int out_size) {
    const float* img = (const float*)d_in[0];
    float* out = (float*)d_out;

    cudaFuncSetAttribute(stt_stage12,
                         cudaFuncAttributeMaxDynamicSharedMemorySize,
                         SMEM_WORDS * 4);

    dim3 g12(NB1, 48);
    stt_stage12<<<g12, 512, SMEM_WORDS * 4>>>(img);

    dim3 g2b(NCG, 48);
    stt_stage2b<<<g2b, 32>>>();

    dim3 g3(NTOK, 48);
    stt_stage3<<<g3, dim3(TS, TS)>>>(out);
}